// round 8
// baseline (speedup 1.0000x reference)
#include <cuda_runtime.h>
#include <cstdint>

// out[b,p,d] = (sum_h hs[b,p,h] * W[prop[b,p], h, d] + bias[prop[b,p], d]) * mask[b,p]
// B=512, P=128 -> 65536 rows, H=512, D=2.
// Two rows per warp, double-buffered via two cp.async commit groups:
//   issue A (4x hs + 8x W), commit; issue B, commit; wait 1; consume A; wait 0; consume B.
// hs stream carries L2::evict_first so the 41MB W table stays L2-resident.

#define NROWS 65536
#define HDIM 512
#define WPB 2            // warps per block
#define ROWS_PER_WARP 2

__global__ __launch_bounds__(32 * WPB) void adapter_kernel(
    const float* __restrict__ hs,          // [65536, 512]
    const int* __restrict__ props,         // [65536] int32
    const float* __restrict__ mask,        // [65536]
    const float* __restrict__ W,           // [10000, 512, 2]
    const float* __restrict__ bias,        // [10000, 2]
    float* __restrict__ out)               // [65536, 2]
{
    __shared__ float4 hbuf[2][WPB][128];   // 2KB per row-slot per warp
    __shared__ float4 wbuf[2][WPB][256];   // 4KB per row-slot per warp

    const int warp = threadIdx.x >> 5;
    const int lane = threadIdx.x & 31;
    const int rowA = (blockIdx.x * WPB + warp) * ROWS_PER_WARP;
    const int rowB = rowA + 1;

    const int pA = __ldg(&props[rowA]);
    const int pB = __ldg(&props[rowB]);

    const float4* __restrict__ h4A = reinterpret_cast<const float4*>(hs + (size_t)rowA * HDIM);
    const float4* __restrict__ h4B = reinterpret_cast<const float4*>(hs + (size_t)rowB * HDIM);
    const float4* __restrict__ w4A = reinterpret_cast<const float4*>(W + (size_t)pA * (HDIM * 2));
    const float4* __restrict__ w4B = reinterpret_cast<const float4*>(W + (size_t)pB * (HDIM * 2));

    // Evict-first policy for the hs stream (protects W residency in L2).
    uint64_t pol;
    asm volatile("createpolicy.fractional.L2::evict_first.b64 %0, 1.0;" : "=l"(pol));

    // ---- issue group A ----
    #pragma unroll
    for (int i = 0; i < 4; i++) {
        uint32_t dst = (uint32_t)__cvta_generic_to_shared(&hbuf[0][warp][i * 32 + lane]);
        asm volatile("cp.async.cg.shared.global.L2::cache_hint [%0], [%1], 16, %2;"
                     :: "r"(dst), "l"(h4A + i * 32 + lane), "l"(pol) : "memory");
    }
    #pragma unroll
    for (int i = 0; i < 8; i++) {
        uint32_t dst = (uint32_t)__cvta_generic_to_shared(&wbuf[0][warp][i * 32 + lane]);
        asm volatile("cp.async.cg.shared.global [%0], [%1], 16;"
                     :: "r"(dst), "l"(w4A + i * 32 + lane) : "memory");
    }
    asm volatile("cp.async.commit_group;" ::: "memory");

    // ---- issue group B ----
    #pragma unroll
    for (int i = 0; i < 4; i++) {
        uint32_t dst = (uint32_t)__cvta_generic_to_shared(&hbuf[1][warp][i * 32 + lane]);
        asm volatile("cp.async.cg.shared.global.L2::cache_hint [%0], [%1], 16, %2;"
                     :: "r"(dst), "l"(h4B + i * 32 + lane), "l"(pol) : "memory");
    }
    #pragma unroll
    for (int i = 0; i < 8; i++) {
        uint32_t dst = (uint32_t)__cvta_generic_to_shared(&wbuf[1][warp][i * 32 + lane]);
        asm volatile("cp.async.cg.shared.global [%0], [%1], 16;"
                     :: "r"(dst), "l"(w4B + i * 32 + lane) : "memory");
    }
    asm volatile("cp.async.commit_group;" ::: "memory");

    // ================= consume A (B still in flight) =================
    asm volatile("cp.async.wait_group 1;" ::: "memory");
    __syncwarp();
    {
        const float2* __restrict__ h2 = reinterpret_cast<const float2*>(hbuf[0][warp]);
        float acc0 = 0.f, acc1 = 0.f;
        #pragma unroll
        for (int j = 0; j < 8; j++) {
            const int idx = j * 32 + lane;
            const float4 wv = wbuf[0][warp][idx];
            const float2 hh = h2[idx];
            acc0 = fmaf(hh.x, wv.x, acc0);
            acc1 = fmaf(hh.x, wv.y, acc1);
            acc0 = fmaf(hh.y, wv.z, acc0);
            acc1 = fmaf(hh.y, wv.w, acc1);
        }
        #pragma unroll
        for (int off = 16; off > 0; off >>= 1) {
            acc0 += __shfl_xor_sync(0xFFFFFFFFu, acc0, off);
            acc1 += __shfl_xor_sync(0xFFFFFFFFu, acc1, off);
        }
        if (lane == 0) {
            const float m = mask[rowA];
            float2 r;
            r.x = (acc0 + __ldg(&bias[pA * 2 + 0])) * m;
            r.y = (acc1 + __ldg(&bias[pA * 2 + 1])) * m;
            __stcs(reinterpret_cast<float2*>(out) + rowA, r);
        }
    }

    // ================= consume B =================
    asm volatile("cp.async.wait_group 0;" ::: "memory");
    __syncwarp();
    {
        const float2* __restrict__ h2 = reinterpret_cast<const float2*>(hbuf[1][warp]);
        float acc0 = 0.f, acc1 = 0.f;
        #pragma unroll
        for (int j = 0; j < 8; j++) {
            const int idx = j * 32 + lane;
            const float4 wv = wbuf[1][warp][idx];
            const float2 hh = h2[idx];
            acc0 = fmaf(hh.x, wv.x, acc0);
            acc1 = fmaf(hh.x, wv.y, acc1);
            acc0 = fmaf(hh.y, wv.z, acc0);
            acc1 = fmaf(hh.y, wv.w, acc1);
        }
        #pragma unroll
        for (int off = 16; off > 0; off >>= 1) {
            acc0 += __shfl_xor_sync(0xFFFFFFFFu, acc0, off);
            acc1 += __shfl_xor_sync(0xFFFFFFFFu, acc1, off);
        }
        if (lane == 0) {
            const float m = mask[rowB];
            float2 r;
            r.x = (acc0 + __ldg(&bias[pB * 2 + 0])) * m;
            r.y = (acc1 + __ldg(&bias[pB * 2 + 1])) * m;
            __stcs(reinterpret_cast<float2*>(out) + rowB, r);
        }
    }
}

extern "C" void kernel_launch(void* const* d_in, const int* in_sizes, int n_in,
                              void* d_out, int out_size)
{
    const float* hs    = (const float*)d_in[0];
    const int*   props = (const int*)d_in[1];
    const float* mask  = (const float*)d_in[2];
    const float* W     = (const float*)d_in[3];
    const float* bias  = (const float*)d_in[4];
    float*       out   = (float*)d_out;

    const int threads = 32 * WPB;
    const int blocks = NROWS / (WPB * ROWS_PER_WARP);
    adapter_kernel<<<blocks, threads>>>(hs, props, mask, W, bias, out);
}